// round 1
// baseline (speedup 1.0000x reference)
#include <cuda_runtime.h>
#include <math_constants.h>

#define NODES_MAX 20000
#define F 128
#define H 4
#define HF 512
#define NRBF 20
#define OUTC 384

// scratch: q, k, v tables (fp32)
__device__ float g_q[NODES_MAX * HF];
__device__ float g_k[NODES_MAX * HF];
__device__ float g_v[NODES_MAX * HF];

__device__ __forceinline__ float silu_f(float x) {
    return x * __fdividef(1.f, 1.f + __expf(-x));
}

// ---------------------------------------------------------------------------
// Kernel 1: LayerNorm + QKV GEMM.  grid (ceil(N/64), 4, 3), block 256.
// A tile: LN'd input transposed [k=128][node=64] (stride 68).
// B tile: weight [k=128][col=128].
// Each thread computes a 4(node) x 8(col) micro-tile.
// ---------------------------------------------------------------------------
__global__ __launch_bounds__(256) void qkv_kernel(
    const float* __restrict__ s_j,
    const float* __restrict__ ln_g, const float* __restrict__ ln_b,
    const float* __restrict__ Wq, const float* __restrict__ bq,
    const float* __restrict__ Wk, const float* __restrict__ bk,
    const float* __restrict__ Wv, const float* __restrict__ bv,
    int n_nodes)
{
    extern __shared__ float sm[];
    float* A = sm;                 // [128][68]
    float* B = sm + 128 * 68;      // [128][128]

    const float* W; const float* bias; float* out;
    if (blockIdx.z == 0)      { W = Wq; bias = bq; out = g_q; }
    else if (blockIdx.z == 1) { W = Wk; bias = bk; out = g_k; }
    else                      { W = Wv; bias = bv; out = g_v; }

    const int tid  = threadIdx.x;
    const int lane = tid & 31;
    const int warp = tid >> 5;
    const int node0 = blockIdx.x * 64;
    const int colt  = blockIdx.y * 128;

    // --- LayerNorm into A (transposed) ---
    float4 g4 = *(const float4*)&ln_g[lane * 4];
    float4 b4 = *(const float4*)&ln_b[lane * 4];
    #pragma unroll
    for (int nn = 0; nn < 8; nn++) {
        int nl = warp * 8 + nn;
        int node = node0 + nl;
        float4 x = make_float4(0.f, 0.f, 0.f, 0.f);
        if (node < n_nodes) x = *(const float4*)&s_j[(size_t)node * F + lane * 4];
        float s  = x.x + x.y + x.z + x.w;
        float s2 = x.x * x.x + x.y * x.y + x.z * x.z + x.w * x.w;
        #pragma unroll
        for (int o = 16; o; o >>= 1) {
            s  += __shfl_xor_sync(0xffffffffu, s,  o);
            s2 += __shfl_xor_sync(0xffffffffu, s2, o);
        }
        float mu  = s * (1.f / F);
        float var = s2 * (1.f / F) - mu * mu;
        float rs  = rsqrtf(var + 1e-5f);
        A[(lane * 4 + 0) * 68 + nl] = (x.x - mu) * rs * g4.x + b4.x;
        A[(lane * 4 + 1) * 68 + nl] = (x.y - mu) * rs * g4.y + b4.y;
        A[(lane * 4 + 2) * 68 + nl] = (x.z - mu) * rs * g4.z + b4.z;
        A[(lane * 4 + 3) * 68 + nl] = (x.w - mu) * rs * g4.w + b4.w;
    }

    // --- Load weight tile [128][128] ---
    #pragma unroll
    for (int it = 0; it < 16; it++) {
        int lin = tid + it * 256;
        int row = lin >> 5;
        int c4  = (lin & 31) * 4;
        *(float4*)&B[row * 128 + c4] =
            *(const float4*)&W[(size_t)row * HF + colt + c4];
    }
    __syncthreads();

    // --- GEMM 64x128, micro 4x8 ---
    const int ng  = tid >> 4;   // 0..15 node groups
    const int cgp = tid & 15;   // 0..15 col groups (8 cols each)
    float acc[4][8];
    #pragma unroll
    for (int i = 0; i < 4; i++)
        #pragma unroll
        for (int j = 0; j < 8; j++) acc[i][j] = 0.f;

    #pragma unroll 4
    for (int k = 0; k < 128; k++) {
        float4 a  = *(float4*)&A[k * 68 + ng * 4];
        float4 b0 = *(float4*)&B[k * 128 + cgp * 8];
        float4 b1 = *(float4*)&B[k * 128 + cgp * 8 + 4];
        float av[4] = {a.x, a.y, a.z, a.w};
        float bv8[8] = {b0.x, b0.y, b0.z, b0.w, b1.x, b1.y, b1.z, b1.w};
        #pragma unroll
        for (int i = 0; i < 4; i++)
            #pragma unroll
            for (int j = 0; j < 8; j++)
                acc[i][j] += av[i] * bv8[j];
    }

    float4 bias0 = *(const float4*)&bias[colt + cgp * 8];
    float4 bias1 = *(const float4*)&bias[colt + cgp * 8 + 4];
    #pragma unroll
    for (int i = 0; i < 4; i++) {
        int node = node0 + ng * 4 + i;
        if (node < n_nodes) {
            float4 o0 = make_float4(acc[i][0] + bias0.x, acc[i][1] + bias0.y,
                                    acc[i][2] + bias0.z, acc[i][3] + bias0.w);
            float4 o1 = make_float4(acc[i][4] + bias1.x, acc[i][5] + bias1.y,
                                    acc[i][6] + bias1.z, acc[i][7] + bias1.w);
            *(float4*)&out[(size_t)node * HF + colt + cgp * 8]     = o0;
            *(float4*)&out[(size_t)node * HF + colt + cgp * 8 + 4] = o1;
        }
    }
}

// ---------------------------------------------------------------------------
// Kernel 2: per-edge rbf -> dk/dv -> attn -> msg -> dense GEMM.
// grid (E/64), block 512. 64 edges per CTA.
// smem: msg [64][516], dk scratch [32][512] (reused as denseW tile [64][128]),
//       rbf [64][20], env [64], ij [128]
// ---------------------------------------------------------------------------
__global__ __launch_bounds__(512) void edge_kernel(
    const float* __restrict__ dist, const int* __restrict__ nbrs,
    const float* __restrict__ dkW, const float* __restrict__ dkb,
    const float* __restrict__ dvW, const float* __restrict__ dvb,
    const float* __restrict__ denseW, const float* __restrict__ denseb,
    float* __restrict__ out)
{
    extern __shared__ float sm[];
    float* msg = sm;                          // 64*516
    float* dks = sm + 64 * 516;               // 32*512 (also w tile 64*128)
    float* rbf = dks + 32 * 512;               // 64*20
    float* env = rbf + 64 * NRBF;              // 64
    int*   ij  = (int*)(env + 64);             // 128

    const int tid  = threadIdx.x;
    const int lane = tid & 31;
    const int warp = tid >> 5;
    const int e0 = blockIdx.x * 64;

    // ---- Phase A: edge metadata ----
    if (tid < 128) ij[tid] = nbrs[(size_t)e0 * 2 + tid];
    if (tid < 64) {
        float d = dist[e0 + tid];
        env[tid] = 0.5f * (cospif(d * 0.2f) + 1.f);
    }
    for (int t = tid; t < 64 * NRBF; t += 512) {
        int e = t / NRBF, r = t % NRBF;
        float d = dist[e0 + e];
        const float delta = 5.f / 19.f;
        float u = (d - (float)r * delta) * (19.f / 5.f);
        rbf[t] = __expf(-0.5f * u * u);
    }

    // preload dkW / dvW columns (thread owns column idx = tid)
    float wk[NRBF], wv[NRBF];
    #pragma unroll
    for (int r = 0; r < NRBF; r++) {
        wk[r] = dkW[r * HF + tid];
        wv[r] = dvW[r * HF + tid];
    }
    const float bk_ = dkb[tid];
    const float bv_ = dvb[tid];
    __syncthreads();

    // ---- Phases B0/B1 in two half-batches of 32 edges ----
    for (int hb = 0; hb < 2; hb++) {
        // B0: dk -> dks, dv -> msg (pre-scale)
        #pragma unroll 2
        for (int el = 0; el < 32; el++) {
            int e = hb * 32 + el;
            float a = bk_, b = bv_;
            #pragma unroll
            for (int r = 0; r < NRBF; r++) {
                float rb = rbf[e * NRBF + r];
                a += rb * wk[r];
                b += rb * wv[r];
            }
            dks[el * 512 + tid] = silu_f(a);
            msg[e * 516 + tid]  = silu_f(b);
        }
        __syncthreads();

        // B1: attention + msg scaling. Each warp handles 2 edges.
        #pragma unroll
        for (int ee = 0; ee < 2; ee++) {
            int el = warp * 2 + ee;       // 0..31
            int e  = hb * 32 + el;
            int i  = ij[2 * e];
            int j  = ij[2 * e + 1];
            const float* qp = g_q + (size_t)i * HF;
            const float* kp = g_k + (size_t)j * HF;
            const float* vp = g_v + (size_t)j * HF;
            #pragma unroll
            for (int h = 0; h < H; h++) {
                int f4 = h * F + lane * 4;
                float4 q4 = *(const float4*)(qp + f4);
                float4 k4 = *(const float4*)(kp + f4);
                float4 v4 = *(const float4*)(vp + f4);
                float4 dk4 = *(float4*)&dks[el * 512 + f4];
                float4 dv4 = *(float4*)&msg[e * 516 + f4];
                float s = q4.x * dk4.x * k4.x + q4.y * dk4.y * k4.y
                        + q4.z * dk4.z * k4.z + q4.w * dk4.w * k4.w;
                #pragma unroll
                for (int o = 16; o; o >>= 1) s += __shfl_xor_sync(0xffffffffu, s, o);
                float attn = silu_f(s) * env[e];
                float4 m;
                m.x = attn * v4.x * dv4.x;
                m.y = attn * v4.y * dv4.y;
                m.z = attn * v4.z * dv4.z;
                m.w = attn * v4.w * dv4.w;
                *(float4*)&msg[e * 516 + f4] = m;
            }
        }
        __syncthreads();
    }

    // ---- Phase C: out[64][384] = msg[64][512] @ denseW[512][384] + denseb ----
    float* ws = dks;                 // reuse as [64][128] tile
    const int cg = tid & 31;         // col group (4 cols)
    const int eg = tid >> 5;         // edge group (4 edges)

    for (int nc = 0; nc < 3; nc++) {
        float acc[4][4];
        #pragma unroll
        for (int a = 0; a < 4; a++)
            #pragma unroll
            for (int b = 0; b < 4; b++) acc[a][b] = 0.f;

        for (int kt = 0; kt < 8; kt++) {
            __syncthreads();
            #pragma unroll
            for (int it = 0; it < 4; it++) {
                int lin = tid + it * 512;
                int row = lin >> 5;
                int c4  = (lin & 31) * 4;
                *(float4*)&ws[row * 128 + c4] =
                    *(const float4*)&denseW[(size_t)(kt * 64 + row) * OUTC + nc * 128 + c4];
            }
            __syncthreads();

            #pragma unroll 4
            for (int kk = 0; kk < 64; kk += 4) {
                float4 w0 = *(float4*)&ws[(kk + 0) * 128 + cg * 4];
                float4 w1 = *(float4*)&ws[(kk + 1) * 128 + cg * 4];
                float4 w2 = *(float4*)&ws[(kk + 2) * 128 + cg * 4];
                float4 w3 = *(float4*)&ws[(kk + 3) * 128 + cg * 4];
                #pragma unroll
                for (int ee = 0; ee < 4; ee++) {
                    float4 m = *(float4*)&msg[(eg * 4 + ee) * 516 + kt * 64 + kk];
                    acc[ee][0] += m.x * w0.x + m.y * w1.x + m.z * w2.x + m.w * w3.x;
                    acc[ee][1] += m.x * w0.y + m.y * w1.y + m.z * w2.y + m.w * w3.y;
                    acc[ee][2] += m.x * w0.z + m.y * w1.z + m.z * w2.z + m.w * w3.z;
                    acc[ee][3] += m.x * w0.w + m.y * w1.w + m.z * w2.w + m.w * w3.w;
                }
            }
        }

        float4 bb = *(const float4*)&denseb[nc * 128 + cg * 4];
        #pragma unroll
        for (int ee = 0; ee < 4; ee++) {
            int e = e0 + eg * 4 + ee;
            float4 o = make_float4(acc[ee][0] + bb.x, acc[ee][1] + bb.y,
                                   acc[ee][2] + bb.z, acc[ee][3] + bb.w);
            *(float4*)&out[(size_t)e * OUTC + nc * 128 + cg * 4] = o;
        }
    }
}

// ---------------------------------------------------------------------------
extern "C" void kernel_launch(void* const* d_in, const int* in_sizes, int n_in,
                              void* d_out, int out_size)
{
    const float* s_j    = (const float*)d_in[0];
    const float* dist   = (const float*)d_in[1];
    const int*   nbrs   = (const int*)  d_in[2];
    const float* ln_g   = (const float*)d_in[3];
    const float* ln_b   = (const float*)d_in[4];
    const float* Wq     = (const float*)d_in[5];
    const float* bq     = (const float*)d_in[6];
    const float* Wk     = (const float*)d_in[7];
    const float* bk     = (const float*)d_in[8];
    const float* Wv     = (const float*)d_in[9];
    const float* bv     = (const float*)d_in[10];
    const float* dkW    = (const float*)d_in[11];
    const float* dkb    = (const float*)d_in[12];
    const float* dvW    = (const float*)d_in[13];
    const float* dvb    = (const float*)d_in[14];
    const float* denseW = (const float*)d_in[15];
    const float* denseb = (const float*)d_in[16];
    float* out = (float*)d_out;

    int n_nodes = in_sizes[0] / F;    // 20000
    int n_edges = in_sizes[1];        // 160000

    const int smem_q = (128 * 68 + 128 * 128) * 4;                  // 100,352 B
    const int smem_e = (64 * 516 + 32 * 512 + 64 * NRBF + 64) * 4
                     + 128 * (int)sizeof(int);                      // 203,520 B

    cudaFuncSetAttribute(qkv_kernel,  cudaFuncAttributeMaxDynamicSharedMemorySize, smem_q);
    cudaFuncSetAttribute(edge_kernel, cudaFuncAttributeMaxDynamicSharedMemorySize, smem_e);

    dim3 gq((n_nodes + 63) / 64, 4, 3);
    qkv_kernel<<<gq, 256, smem_q>>>(s_j, ln_g, ln_b, Wq, bq, Wk, bk, Wv, bv, n_nodes);

    edge_kernel<<<n_edges / 64, 512, smem_e>>>(
        dist, nbrs, dkW, dkb, dvW, dvb, denseW, denseb, out);
}

// round 3
// speedup vs baseline: 1.6504x; 1.6504x over previous
#include <cuda_runtime.h>
#include <cuda_bf16.h>
#include <cstdint>

#define F 128
#define H 4
#define HF 512
#define NRBF 20
#define OUTC 384
#define NODES_MAX 20000
#define EPC 64

// device scratch
__device__ float g_q[NODES_MAX * HF];
__device__ float g_k[NODES_MAX * HF];
__device__ float g_v[NODES_MAX * HF];
__device__ __nv_bfloat16 g_Bhi[OUTC * HF];   // denseW^T hi, [n][k]
__device__ __nv_bfloat16 g_Blo[OUTC * HF];   // denseW^T lo, [n][k]

__device__ __forceinline__ float silu_f(float x) {
    return x * __fdividef(1.f, 1.f + __expf(-x));
}
__device__ __forceinline__ uint32_t smem_u32(const void* p) {
    uint32_t a;
    asm("{ .reg .u64 t; cvta.to.shared.u64 t, %1; cvt.u32.u64 %0, t; }"
        : "=r"(a) : "l"(p));
    return a;
}
__device__ __forceinline__ void ldsm_x4(uint32_t& r0, uint32_t& r1, uint32_t& r2,
                                        uint32_t& r3, uint32_t addr) {
    asm volatile("ldmatrix.sync.aligned.m8n8.x4.shared.b16 {%0,%1,%2,%3}, [%4];"
                 : "=r"(r0), "=r"(r1), "=r"(r2), "=r"(r3) : "r"(addr));
}
__device__ __forceinline__ void mma16816(float* c, const uint32_t* a,
                                         uint32_t b0, uint32_t b1) {
    asm volatile(
        "mma.sync.aligned.m16n8k16.row.col.f32.bf16.bf16.f32 "
        "{%0,%1,%2,%3},{%4,%5,%6,%7},{%8,%9},{%0,%1,%2,%3};"
        : "+f"(c[0]), "+f"(c[1]), "+f"(c[2]), "+f"(c[3])
        : "r"(a[0]), "r"(a[1]), "r"(a[2]), "r"(a[3]), "r"(b0), "r"(b1));
}

// ---------------------------------------------------------------------------
// Kernel 0: transpose + bf16-split denseW [512,384] -> g_Bhi/g_Blo [384][512]
// ---------------------------------------------------------------------------
__global__ void prep_kernel(const float* __restrict__ denseW) {
    int n = blockIdx.x;       // 0..383
    int k = threadIdx.x;      // 0..511
    float wv = denseW[(size_t)k * OUTC + n];
    __nv_bfloat16 hi = __float2bfloat16_rn(wv);
    g_Bhi[n * HF + k] = hi;
    g_Blo[n * HF + k] = __float2bfloat16_rn(wv - __bfloat162float(hi));
}

// ---------------------------------------------------------------------------
// Kernel 1: LayerNorm + QKV GEMM (unchanged, proven)
// ---------------------------------------------------------------------------
__global__ __launch_bounds__(256) void qkv_kernel(
    const float* __restrict__ s_j,
    const float* __restrict__ ln_g, const float* __restrict__ ln_b,
    const float* __restrict__ Wq, const float* __restrict__ bq,
    const float* __restrict__ Wk, const float* __restrict__ bk,
    const float* __restrict__ Wv, const float* __restrict__ bv,
    int n_nodes)
{
    extern __shared__ float sm[];
    float* A = sm;                 // [128][68]
    float* B = sm + 128 * 68;      // [128][128]

    const float* W; const float* bias; float* outp;
    if (blockIdx.z == 0)      { W = Wq; bias = bq; outp = g_q; }
    else if (blockIdx.z == 1) { W = Wk; bias = bk; outp = g_k; }
    else                      { W = Wv; bias = bv; outp = g_v; }

    const int tid  = threadIdx.x;
    const int lane = tid & 31;
    const int warp = tid >> 5;
    const int node0 = blockIdx.x * 64;
    const int colt  = blockIdx.y * 128;

    float4 g4 = *(const float4*)&ln_g[lane * 4];
    float4 b4 = *(const float4*)&ln_b[lane * 4];
    #pragma unroll
    for (int nn = 0; nn < 8; nn++) {
        int nl = warp * 8 + nn;
        int node = node0 + nl;
        float4 x = make_float4(0.f, 0.f, 0.f, 0.f);
        if (node < n_nodes) x = *(const float4*)&s_j[(size_t)node * F + lane * 4];
        float s  = x.x + x.y + x.z + x.w;
        float s2 = x.x * x.x + x.y * x.y + x.z * x.z + x.w * x.w;
        #pragma unroll
        for (int o = 16; o; o >>= 1) {
            s  += __shfl_xor_sync(0xffffffffu, s,  o);
            s2 += __shfl_xor_sync(0xffffffffu, s2, o);
        }
        float mu  = s * (1.f / F);
        float var = s2 * (1.f / F) - mu * mu;
        float rs  = rsqrtf(var + 1e-5f);
        A[(lane * 4 + 0) * 68 + nl] = (x.x - mu) * rs * g4.x + b4.x;
        A[(lane * 4 + 1) * 68 + nl] = (x.y - mu) * rs * g4.y + b4.y;
        A[(lane * 4 + 2) * 68 + nl] = (x.z - mu) * rs * g4.z + b4.z;
        A[(lane * 4 + 3) * 68 + nl] = (x.w - mu) * rs * g4.w + b4.w;
    }

    #pragma unroll
    for (int it = 0; it < 16; it++) {
        int lin = tid + it * 256;
        int row = lin >> 5;
        int c4  = (lin & 31) * 4;
        *(float4*)&B[row * 128 + c4] =
            *(const float4*)&W[(size_t)row * HF + colt + c4];
    }
    __syncthreads();

    const int ng  = tid >> 4;
    const int cgp = tid & 15;
    float acc[4][8];
    #pragma unroll
    for (int i = 0; i < 4; i++)
        #pragma unroll
        for (int j = 0; j < 8; j++) acc[i][j] = 0.f;

    #pragma unroll 4
    for (int k = 0; k < 128; k++) {
        float4 a  = *(float4*)&A[k * 68 + ng * 4];
        float4 b0 = *(float4*)&B[k * 128 + cgp * 8];
        float4 b1 = *(float4*)&B[k * 128 + cgp * 8 + 4];
        float av[4] = {a.x, a.y, a.z, a.w};
        float bv8[8] = {b0.x, b0.y, b0.z, b0.w, b1.x, b1.y, b1.z, b1.w};
        #pragma unroll
        for (int i = 0; i < 4; i++)
            #pragma unroll
            for (int j = 0; j < 8; j++)
                acc[i][j] += av[i] * bv8[j];
    }

    float4 bias0 = *(const float4*)&bias[colt + cgp * 8];
    float4 bias1 = *(const float4*)&bias[colt + cgp * 8 + 4];
    #pragma unroll
    for (int i = 0; i < 4; i++) {
        int node = node0 + ng * 4 + i;
        if (node < n_nodes) {
            float4 o0 = make_float4(acc[i][0] + bias0.x, acc[i][1] + bias0.y,
                                    acc[i][2] + bias0.z, acc[i][3] + bias0.w);
            float4 o1 = make_float4(acc[i][4] + bias1.x, acc[i][5] + bias1.y,
                                    acc[i][6] + bias1.z, acc[i][7] + bias1.w);
            *(float4*)&outp[(size_t)node * HF + colt + cgp * 8]     = o0;
            *(float4*)&outp[(size_t)node * HF + colt + cgp * 8 + 4] = o1;
        }
    }
}

// ---------------------------------------------------------------------------
// Kernel 2: edge kernel. Phases A/B (R1, proven) + phase C via mma.sync bf16x3
// grid = E/64, block 512.
// smem (floats):
//   msg:    [0, 33024)             64x516 fp32
//   scratch:[33024, 50944)         71680 B:
//       phase B: dks [32][512] fp32 (65536 B)
//       phase C: Bhi(30720) Blo(30720) Ahi(5120) Alo(5120)  @ byte 132096
//   rbf:    [50944, 52224)  env: [52224, 52288)  ij(int): [52288, 52416)
// total 209664 B
// ---------------------------------------------------------------------------
#define SMEM_EDGE 209664

__global__ __launch_bounds__(512) void edge_kernel(
    const float* __restrict__ dist, const int* __restrict__ nbrs,
    const float* __restrict__ dkW, const float* __restrict__ dkb,
    const float* __restrict__ dvW, const float* __restrict__ dvb,
    const float* __restrict__ denseb,
    float* __restrict__ out)
{
    extern __shared__ float sm[];
    float* msg = sm;                  // 64*516
    float* dks = sm + 33024;          // phase-B scratch
    float* rbf = sm + 50944;          // 64*20
    float* env = sm + 52224;          // 64
    int*   ij  = (int*)(sm + 52288);  // 128

    char* smc = (char*)sm;
    const uint32_t smb = smem_u32(sm);
    const uint32_t aBhi = smb + 132096u;
    const uint32_t aBlo = aBhi + 30720u;
    const uint32_t aAhi = aBlo + 30720u;
    const uint32_t aAlo = aAhi + 5120u;

    const int tid  = threadIdx.x;
    const int lane = tid & 31;
    const int warp = tid >> 5;
    const int e0 = blockIdx.x * 64;

    // ---- Phase A: edge metadata ----
    if (tid < 128) ij[tid] = nbrs[(size_t)e0 * 2 + tid];
    if (tid < 64) {
        float d = dist[e0 + tid];
        env[tid] = 0.5f * (cospif(d * 0.2f) + 1.f);
    }
    for (int t = tid; t < 64 * NRBF; t += 512) {
        int e = t / NRBF, r = t % NRBF;
        float d = dist[e0 + e];
        float u = (d - (float)r * (5.f / 19.f)) * (19.f / 5.f);
        rbf[t] = __expf(-0.5f * u * u);
    }

    float wk[NRBF], wv[NRBF];
    #pragma unroll
    for (int r = 0; r < NRBF; r++) {
        wk[r] = dkW[r * HF + tid];
        wv[r] = dvW[r * HF + tid];
    }
    const float bk_ = dkb[tid];
    const float bv_ = dvb[tid];
    __syncthreads();

    // ---- Phases B0/B1 ----
    for (int hb = 0; hb < 2; hb++) {
        #pragma unroll 2
        for (int el = 0; el < 32; el++) {
            int e = hb * 32 + el;
            float a = bk_, b = bv_;
            #pragma unroll
            for (int r = 0; r < NRBF; r++) {
                float rb = rbf[e * NRBF + r];
                a += rb * wk[r];
                b += rb * wv[r];
            }
            dks[el * 512 + tid] = silu_f(a);
            msg[e * 516 + tid]  = silu_f(b);
        }
        __syncthreads();

        #pragma unroll
        for (int ee = 0; ee < 2; ee++) {
            int el = warp * 2 + ee;
            int e  = hb * 32 + el;
            int i  = ij[2 * e];
            int j  = ij[2 * e + 1];
            const float* qp = g_q + (size_t)i * HF;
            const float* kp = g_k + (size_t)j * HF;
            const float* vp = g_v + (size_t)j * HF;
            #pragma unroll
            for (int h = 0; h < H; h++) {
                int f4 = h * F + lane * 4;
                float4 q4 = *(const float4*)(qp + f4);
                float4 k4 = *(const float4*)(kp + f4);
                float4 v4 = *(const float4*)(vp + f4);
                float4 dk4 = *(float4*)&dks[el * 512 + f4];
                float4 dv4 = *(float4*)&msg[e * 516 + f4];
                float s = q4.x * dk4.x * k4.x + q4.y * dk4.y * k4.y
                        + q4.z * dk4.z * k4.z + q4.w * dk4.w * k4.w;
                #pragma unroll
                for (int o = 16; o; o >>= 1) s += __shfl_xor_sync(0xffffffffu, s, o);
                float attn = silu_f(s) * env[e];
                float4 m;
                m.x = attn * v4.x * dv4.x;
                m.y = attn * v4.y * dv4.y;
                m.z = attn * v4.z * dv4.z;
                m.w = attn * v4.w * dv4.w;
                *(float4*)&msg[e * 516 + f4] = m;
            }
        }
        __syncthreads();
    }

    // ---- Phase C: out[64][384] = msg @ denseW + b, bf16x3 mma.sync ----
    const int wm = warp >> 2;            // 0..3  (m16 tile)
    const int wn = warp & 3;             // 0..3  (n96 range)
    float acc[12][4];
    #pragma unroll
    for (int f = 0; f < 12; f++)
        #pragma unroll
        for (int q = 0; q < 4; q++) acc[f][q] = 0.f;

    // per-lane ldmatrix address offsets (constant over chunks)
    const uint32_t aoff = (uint32_t)((wm * 16 + (lane & 15)) * 40 + ((lane >> 4) * 8)) * 2u;
    const uint32_t brow = (uint32_t)((lane & 7) + ((lane >> 4) & 1) * 8);
    const uint32_t bcof = (uint32_t)(((lane >> 3) & 1) * 8);

    // A-conversion indices
    const int ce = tid >> 3;             // edge 0..63
    const int ck = (tid & 7) * 4;        // k 0..28

    for (int c = 0; c < 16; c++) {
        __syncthreads();   // prior chunk's ldmatrix reads done; msg ready (c==0)

        // convert A chunk: msg[:, c*32 .. +32) -> Ahi/Alo bf16 [64][40]
        {
            float4 m = *(float4*)&msg[ce * 516 + c * 32 + ck];
            __nv_bfloat162 h01 = __float22bfloat162_rn(make_float2(m.x, m.y));
            __nv_bfloat162 h23 = __float22bfloat162_rn(make_float2(m.z, m.w));
            float2 l01 = make_float2(m.x - __bfloat162float(h01.x),
                                     m.y - __bfloat162float(h01.y));
            float2 l23 = make_float2(m.z - __bfloat162float(h23.x),
                                     m.w - __bfloat162float(h23.y));
            __nv_bfloat162 lo01 = __float22bfloat162_rn(l01);
            __nv_bfloat162 lo23 = __float22bfloat162_rn(l23);
            uint32_t off = (uint32_t)(ce * 40 + ck) * 2u;
            uint2 hv, lv;
            hv.x = *(uint32_t*)&h01;  hv.y = *(uint32_t*)&h23;
            lv.x = *(uint32_t*)&lo01; lv.y = *(uint32_t*)&lo23;
            *(uint2*)(smc + (aAhi - smb) + off) = hv;
            *(uint2*)(smc + (aAlo - smb) + off) = lv;
        }

        // load B chunk: g_Bhi/g_Blo[:, c*32 .. +32) -> [384][40] bf16
        #pragma unroll
        for (int it = 0; it < 3; it++) {
            int s = it * 512 + tid;
            int n = s >> 2, q = s & 3;
            size_t go = ((size_t)n * HF + c * 32 + q * 8) * 2;
            uint32_t so = (uint32_t)(n * 40 + q * 8) * 2u;
            *(float4*)(smc + (aBhi - smb) + so) = *(const float4*)((const char*)g_Bhi + go);
            *(float4*)(smc + (aBlo - smb) + so) = *(const float4*)((const char*)g_Blo + go);
        }
        __syncthreads();

        // mma: 2 k16 steps
        #pragma unroll
        for (int s = 0; s < 2; s++) {
            uint32_t ah[4], al[4];
            ldsm_x4(ah[0], ah[1], ah[2], ah[3], aAhi + aoff + s * 32);
            ldsm_x4(al[0], al[1], al[2], al[3], aAlo + aoff + s * 32);
            #pragma unroll
            for (int f2 = 0; f2 < 6; f2++) {
                uint32_t n0 = (uint32_t)(wn * 96 + f2 * 16);
                uint32_t boff = ((n0 + brow) * 40 + bcof) * 2u + s * 32;
                uint32_t bh[4], bl[4];
                ldsm_x4(bh[0], bh[1], bh[2], bh[3], aBhi + boff);
                ldsm_x4(bl[0], bl[1], bl[2], bl[3], aBlo + boff);
                mma16816(acc[2 * f2],     ah, bh[0], bh[1]);
                mma16816(acc[2 * f2 + 1], ah, bh[2], bh[3]);
                mma16816(acc[2 * f2],     ah, bl[0], bl[1]);
                mma16816(acc[2 * f2 + 1], ah, bl[2], bl[3]);
                mma16816(acc[2 * f2],     al, bh[0], bh[1]);
                mma16816(acc[2 * f2 + 1], al, bh[2], bh[3]);
            }
        }
    }

    // ---- epilogue ----
    {
        const int g   = lane >> 2;
        const int tig = lane & 3;
        const size_t r0 = (size_t)(e0 + wm * 16 + g) * OUTC;
        const size_t r1 = r0 + 8 * OUTC;
        #pragma unroll
        for (int f = 0; f < 12; f++) {
            int col = wn * 96 + f * 8 + tig * 2;
            float2 b2 = *(const float2*)&denseb[col];
            float2 o0 = make_float2(acc[f][0] + b2.x, acc[f][1] + b2.y);
            float2 o1 = make_float2(acc[f][2] + b2.x, acc[f][3] + b2.y);
            *(float2*)&out[r0 + col] = o0;
            *(float2*)&out[r1 + col] = o1;
        }
    }
}

// ---------------------------------------------------------------------------
extern "C" void kernel_launch(void* const* d_in, const int* in_sizes, int n_in,
                              void* d_out, int out_size)
{
    const float* s_j    = (const float*)d_in[0];
    const float* dist   = (const float*)d_in[1];
    const int*   nbrs   = (const int*)  d_in[2];
    const float* ln_g   = (const float*)d_in[3];
    const float* ln_b   = (const float*)d_in[4];
    const float* Wq     = (const float*)d_in[5];
    const float* bq     = (const float*)d_in[6];
    const float* Wk     = (const float*)d_in[7];
    const float* bk     = (const float*)d_in[8];
    const float* Wv     = (const float*)d_in[9];
    const float* bv     = (const float*)d_in[10];
    const float* dkW    = (const float*)d_in[11];
    const float* dkb    = (const float*)d_in[12];
    const float* dvW    = (const float*)d_in[13];
    const float* dvb    = (const float*)d_in[14];
    const float* denseW = (const float*)d_in[15];
    const float* denseb = (const float*)d_in[16];
    float* out = (float*)d_out;

    int n_nodes = in_sizes[0] / F;    // 20000
    int n_edges = in_sizes[1];        // 160000

    const int smem_q = (128 * 68 + 128 * 128) * 4;

    cudaFuncSetAttribute(qkv_kernel,  cudaFuncAttributeMaxDynamicSharedMemorySize, smem_q);
    cudaFuncSetAttribute(edge_kernel, cudaFuncAttributeMaxDynamicSharedMemorySize, SMEM_EDGE);

    prep_kernel<<<OUTC, HF>>>(denseW);

    dim3 gq((n_nodes + 63) / 64, 4, 3);
    qkv_kernel<<<gq, 256, smem_q>>>(s_j, ln_g, ln_b, Wq, bq, Wk, bk, Wv, bv, n_nodes);

    edge_kernel<<<n_edges / EPC, 512, SMEM_EDGE>>>(
        dist, nbrs, dkW, dkb, dvW, dvb, denseb, out);
}